// round 13
// baseline (speedup 1.0000x reference)
#include <cuda_runtime.h>
#include <cuda_bf16.h>
#include <math.h>

// Problem constants (fixed by the dataset)
#define B_DIM 8
#define H_DIM 32
#define D_DIM 128
#define PAGE_SIZE 16
#define PAGES_PER_SEQ 512
#define L_MAX 4096

#define TILE 128                  // fixed indices per block (work tile)
#define SPLIT_MAX (L_MAX / TILE)  // 32 slots per (b,h)
#define NWARPS 4
#define NTHREADS (NWARPS * 32)    // 128
#define GDEPTH 2                  // ring slots (groups) per warp
#define GSIZE 8                   // indices per group (quad-per-row layout)

#define KV_STRIDE 16384u          // floats between K and V of same page/head

// Split-K scratch: per (bh, slot) partial softmax state
__device__ float g_m[B_DIM * H_DIM * SPLIT_MAX];
__device__ float g_s[B_DIM * H_DIM * SPLIT_MAX];
__device__ float g_acc[B_DIM * H_DIM * SPLIT_MAX * D_DIM];
__device__ unsigned int g_cnt[B_DIM * H_DIM];   // zero-init; reset after use

__device__ __forceinline__ unsigned smem_u32(const void* p) {
    return (unsigned)__cvta_generic_to_shared(p);
}
#define CP16(dst, src) \
    asm volatile("cp.async.cg.shared.global [%0], [%1], 16;" :: "r"(dst), "l"(src))
#define CP16_ZERO(dst, src) \
    asm volatile("cp.async.cg.shared.global [%0], [%1], 16, 0;" :: "r"(dst), "l"(src))
#define CP_COMMIT()  asm volatile("cp.async.commit_group;")
#define CP_WAIT1()   asm volatile("cp.async.wait_group 1;")
#define CP_WAITALL() asm volatile("cp.async.wait_all;")

// Dynamic shared memory layout (68.2 KB -> 3 blocks/SM)
struct Smem {
    // per-warp ring: [warp][stage][K/V][row][d]; rows XOR-swizzled by (row&7)
    float ring[NWARPS][GDEPTH][2][GSIZE][D_DIM];   // 64 KB
    int   pages[PAGES_PER_SEQ];                    // 2 KB
    int   ind[TILE];
    float m[NWARPS];
    float s[NWARPS];
    float acc[NWARPS][D_DIM];                      // 2 KB
    int   is_last;
};

__global__ __launch_bounds__(NTHREADS, 3)
void sparse_attn_kernel(
    const float* __restrict__ q,             // (B,H,1,D)
    const float* __restrict__ kv,            // (total_pages,2,KVH,PS,D)
    const int*   __restrict__ indptr,        // (B+1)
    const int*   __restrict__ page_indices,  // (total_pages)
    const int*   __restrict__ sparse_ind,    // (B,H,L_MAX)
    const int*   __restrict__ sparse_nnz,    // (B,H)
    float*       __restrict__ out)           // (B,H,1,D)
{
    extern __shared__ char smem_raw[];
    Smem& sm = *reinterpret_cast<Smem*>(smem_raw);

    const int blk  = blockIdx.x;
    const int bh   = blk >> 5;               // / SPLIT_MAX
    const int sp   = blk & (SPLIT_MAX - 1);
    const int b    = bh >> 5;                // H=32
    const int h    = bh & 31;
    const int kvh  = h >> 2;                 // groups=4
    const int tid  = threadIdx.x;
    const int wid  = tid >> 5;
    const int lane = tid & 31;

    const int nnz   = sparse_nnz[bh];
    const int start = sp * TILE;
    const int cnt   = min(nnz - start, TILE);   // may be <= 0 (empty tile)

    if (cnt > 0) {
        // Stage page-table segment for this batch (512 ints)
        {
            const int p0 = indptr[b];
            #pragma unroll
            for (int i = tid; i < PAGES_PER_SEQ; i += NTHREADS)
                sm.pages[i] = page_indices[p0 + i];
        }
        // Stage this tile of the sparse index row
        {
            const int* ind_row = sparse_ind + (size_t)bh * L_MAX + start;
            for (int i = tid; i < cnt; i += NTHREADS)
                sm.ind[i] = ind_row[i];
        }

        // Quad layout: lane owns row r = lane&7 of each group, dim quarter
        // s = lane>>3 (dims s*32 .. s*32+31).
        const int r = lane & 7;
        const int s = lane >> 3;

        // q fragment for the score phase: dims s*32 + k*4 .. +4, k=0..7
        float4 qf[8];
        {
            const float4* qv = (const float4*)(q + (size_t)bh * D_DIM + s * 32);
            #pragma unroll
            for (int k = 0; k < 8; k++) qf[k] = qv[k];
        }
        __syncthreads();

        const float scale = 0.08838834764831845f;  // 1/sqrt(128)

        float  m    = -1e30f;
        float  ssum = 0.0f;
        float4 acc  = make_float4(0.f, 0.f, 0.f, 0.f);

        // Warp w owns groups g = w, w+NWARPS, ... ; group g covers l = 8g..8g+7
        const int total_groups = (cnt + GSIZE - 1) >> 3;
        const int n_w = (total_groups > wid)
                      ? (total_groups - wid + NWARPS - 1) / NWARPS : 0;

        const unsigned ring0 = smem_u32(&sm.ring[wid][0][0][0][0]);
        const unsigned slot_bytes = 2u * GSIZE * D_DIM * 4u;   // 8 KB per stage

        // ---- issue one group (t-th local group) into ring stage t&1 ----
        auto issue_group = [&](int t) {
            const int      l0   = (wid + t * NWARPS) * GSIZE;
            const unsigned base = ring0 + (unsigned)(t & 1) * slot_bytes;
            #pragma unroll
            for (int u = 0; u < GSIZE; u++) {
                const int  l     = l0 + u;
                const bool valid = (l < cnt);
                const int  i     = valid ? sm.ind[l] : 0;
                const unsigned page = (unsigned)sm.pages[i >> 4];
                const float* src = kv + ((page << 15)
                                       + ((unsigned)kvh << 11)
                                       + ((unsigned)(i & 15) << 7)
                                       + ((unsigned)lane << 2));
                // logical 16B chunk `lane` stored at physical chunk lane^u
                const unsigned dk = base + (unsigned)u * (D_DIM * 4u)
                                  + (unsigned)((lane ^ u) << 4);
                const unsigned dv = dk + (unsigned)(GSIZE * D_DIM * 4u);
                if (valid) {
                    CP16(dk, src);
                    CP16(dv, src + KV_STRIDE);
                } else {
                    CP16_ZERO(dk, src);
                    CP16_ZERO(dv, src);
                }
            }
            CP_COMMIT();
        };

        if (n_w > 0) {
            issue_group(0);
            issue_group(1);

            for (int t = 0; t < n_w; t++) {
                CP_WAIT1();          // oldest group (t) complete
                __syncwarp();

                const int l0   = (wid + t * NWARPS) * GSIZE;
                const int slot = t & 1;

                // ---- score: each lane dots 32 dims of row r ----
                const float* krow = &sm.ring[wid][slot][0][r][0];
                float d = 0.0f;
                #pragma unroll
                for (int k = 0; k < 8; k++) {
                    const int pc = (s * 8 + k) ^ r;     // physical chunk
                    const float4 kk = *(const float4*)(krow + pc * 4);
                    d += kk.x * qf[k].x + kk.y * qf[k].y
                       + kk.z * qf[k].z + kk.w * qf[k].w;
                }
                // quad reduce across dim-quarters (lanes r, r+8, r+16, r+24)
                d += __shfl_xor_sync(0xffffffffu, d, 8);
                d += __shfl_xor_sync(0xffffffffu, d, 16);
                const float sc = (l0 + r < cnt) ? d * scale : -1e30f;

                // broadcast the 8 scores (lanes 0..7 hold rows 0..7)
                float scu[GSIZE];
                #pragma unroll
                for (int u = 0; u < GSIZE; u++)
                    scu[u] = __shfl_sync(0xffffffffu, sc, u);

                // ---- V rows: lane owns dims lane*4..+4 (logical chunk lane) ----
                const float* vbase = &sm.ring[wid][slot][1][0][0];
                float4 vv[GSIZE];
                #pragma unroll
                for (int u = 0; u < GSIZE; u++)
                    vv[u] = *(const float4*)(vbase + u * D_DIM + ((lane ^ u) << 2));

                __syncwarp();        // all lanes done reading this stage
                issue_group(t + 2);  // refill stage

                // ---- batched online softmax over the 8 indices ----
                float mnew = m;
                #pragma unroll
                for (int u = 0; u < GSIZE; u++) mnew = fmaxf(mnew, scu[u]);

                const float alpha = __expf(m - mnew);
                float p[GSIZE];
                float psum = 0.0f;
                #pragma unroll
                for (int u = 0; u < GSIZE; u++) {
                    p[u] = __expf(scu[u] - mnew);
                    psum += p[u];
                }

                acc.x *= alpha; acc.y *= alpha; acc.z *= alpha; acc.w *= alpha;
                #pragma unroll
                for (int u = 0; u < GSIZE; u++) {
                    acc.x += p[u] * vv[u].x;
                    acc.y += p[u] * vv[u].y;
                    acc.z += p[u] * vv[u].z;
                    acc.w += p[u] * vv[u].w;
                }
                ssum = ssum * alpha + psum;
                m    = mnew;
            }
        }
        CP_WAITALL();   // drain dummy in-flight groups before smem reuse/exit

        // Publish per-warp partials to smem (lane owns dims lane*4..+4)
        sm.acc[wid][lane * 4 + 0] = acc.x;
        sm.acc[wid][lane * 4 + 1] = acc.y;
        sm.acc[wid][lane * 4 + 2] = acc.z;
        sm.acc[wid][lane * 4 + 3] = acc.w;
        if (lane == 0) { sm.m[wid] = m; sm.s[wid] = ssum; }
        __syncthreads();

        // Cross-warp merge -> global split-K partial (128 threads, one per d)
        {
            float M = -1e30f;
            #pragma unroll
            for (int w = 0; w < NWARPS; w++) M = fmaxf(M, sm.m[w]);
            float denom = 0.f, num = 0.f;
            #pragma unroll
            for (int w = 0; w < NWARPS; w++) {
                const float c = __expf(sm.m[w] - M);
                denom += c * sm.s[w];
                num   += c * sm.acc[w][tid];
            }
            g_acc[(size_t)blk * D_DIM + tid] = num;
            if (tid == 0) { g_m[blk] = M; g_s[blk] = denom; }
        }
    } else {
        // Empty tile: publish -inf max so merge weight underflows to exactly 0.
        if (tid == 0) g_m[blk] = -1e30f;
    }

    // Arrival protocol: last block of this bh does the final merge
    __syncthreads();
    if (tid == 0) {
        __threadfence();
        const unsigned old = atomicAdd(&g_cnt[bh], 1u);
        sm.is_last = (old == SPLIT_MAX - 1);
        if (sm.is_last) g_cnt[bh] = 0;   // reset for next graph replay
    }
    __syncthreads();

    if (sm.is_last) {
        __threadfence();   // acquire: make other blocks' fenced writes visible
        const int base = bh * SPLIT_MAX;
        float M = -1e30f;
        #pragma unroll
        for (int s2 = 0; s2 < SPLIT_MAX; s2++) M = fmaxf(M, g_m[base + s2]);
        float denom = 0.f, num = 0.f;
        #pragma unroll
        for (int s2 = 0; s2 < SPLIT_MAX; s2++) {
            const float c = __expf(g_m[base + s2] - M);
            denom += c * g_s[base + s2];
            num   += c * g_acc[(size_t)(base + s2) * D_DIM + tid];
        }
        out[(size_t)bh * D_DIM + tid] = num / denom;
    }
}

extern "C" void kernel_launch(void* const* d_in, const int* in_sizes, int n_in,
                              void* d_out, int out_size) {
    const float* q            = (const float*)d_in[0];
    const float* kv           = (const float*)d_in[1];
    const int*   indptr       = (const int*)d_in[2];
    const int*   page_indices = (const int*)d_in[3];
    const int*   sparse_ind   = (const int*)d_in[4];
    const int*   sparse_nnz   = (const int*)d_in[5];
    float*       out          = (float*)d_out;

    static bool attr_set = false;
    if (!attr_set) {
        cudaFuncSetAttribute(sparse_attn_kernel,
                             cudaFuncAttributeMaxDynamicSharedMemorySize,
                             (int)sizeof(Smem));
        attr_set = true;
    }

    sparse_attn_kernel<<<B_DIM * H_DIM * SPLIT_MAX, NTHREADS, sizeof(Smem)>>>(
        q, kv, indptr, page_indices, sparse_ind, sparse_nnz, out);
}

// round 14
// speedup vs baseline: 1.2620x; 1.2620x over previous
#include <cuda_runtime.h>
#include <cuda_bf16.h>
#include <math.h>

// Problem constants (fixed by the dataset)
#define B_DIM 8
#define H_DIM 32
#define D_DIM 128
#define PAGE_SIZE 16
#define PAGES_PER_SEQ 512
#define L_MAX 4096

#define TILE 256                  // fixed indices per block (work tile)
#define SPLIT_MAX (L_MAX / TILE)  // 16 slots per (b,h)
#define NWARPS 4
#define NTHREADS (NWARPS * 32)    // 128
#define GDEPTH 2                  // ring stages per warp
#define GSIZE 4                   // indices per group

#define KV_STRIDE 16384u          // floats between K and V of same page/head

// Split-K scratch: per (bh, slot) partial softmax state
__device__ float g_m[B_DIM * H_DIM * SPLIT_MAX];
__device__ float g_s[B_DIM * H_DIM * SPLIT_MAX];
__device__ float g_acc[B_DIM * H_DIM * SPLIT_MAX * D_DIM];
__device__ unsigned int g_cnt[B_DIM * H_DIM];   // zero-init; reset after use

__device__ __forceinline__ unsigned smem_u32(const void* p) {
    return (unsigned)__cvta_generic_to_shared(p);
}
#define CP16(dst, src) \
    asm volatile("cp.async.cg.shared.global [%0], [%1], 16;" :: "r"(dst), "l"(src))
#define CP16_ZERO(dst, src) \
    asm volatile("cp.async.cg.shared.global [%0], [%1], 16, 0;" :: "r"(dst), "l"(src))
#define CP_COMMIT()  asm volatile("cp.async.commit_group;")
#define CP_WAIT1()   asm volatile("cp.async.wait_group 1;")
#define CP_WAITALL() asm volatile("cp.async.wait_all;")

__global__ __launch_bounds__(NTHREADS, 6)
void sparse_attn_kernel(
    const float* __restrict__ q,             // (B,H,1,D)
    const float* __restrict__ kv,            // (total_pages,2,KVH,PS,D)
    const int*   __restrict__ indptr,        // (B+1)
    const int*   __restrict__ page_indices,  // (total_pages)
    const int*   __restrict__ sparse_ind,    // (B,H,L_MAX)
    const int*   __restrict__ sparse_nnz,    // (B,H)
    float*       __restrict__ out)           // (B,H,1,D)
{
    const int blk  = blockIdx.x;
    const int bh   = blk >> 4;               // / SPLIT_MAX
    const int sp   = blk & (SPLIT_MAX - 1);
    const int b    = bh >> 5;                // H=32
    const int h    = bh & 31;
    const int kvh  = h >> 2;                 // groups=4
    const int tid  = threadIdx.x;
    const int wid  = tid >> 5;
    const int lane = tid & 31;

    __shared__ int   s_pages[PAGES_PER_SEQ];
    __shared__ int   s_ind[TILE];
    // per-warp ring: [warp][stage][K/V][idx-in-group][d]
    __shared__ float s_ring[NWARPS][GDEPTH][2][GSIZE][D_DIM];
    __shared__ float s_m[NWARPS];
    __shared__ float s_s[NWARPS];
    __shared__ float s_acc[NWARPS][D_DIM];
    __shared__ int   s_is_last;

    const int nnz   = sparse_nnz[bh];
    const int start = sp * TILE;
    const int cnt   = min(nnz - start, TILE);   // may be <= 0 (empty tile)

    if (cnt > 0) {
        // Stage page-table segment for this batch (512 ints)
        {
            const int p0 = indptr[b];
            #pragma unroll
            for (int i = tid; i < PAGES_PER_SEQ; i += NTHREADS)
                s_pages[i] = page_indices[p0 + i];
        }
        // Stage this tile of the sparse index row
        {
            const int* ind_row = sparse_ind + (size_t)bh * L_MAX + start;
            for (int i = tid; i < cnt; i += NTHREADS)
                s_ind[i] = ind_row[i];
        }

        // q fragment: lane owns d = [lane*4, lane*4+4)
        float4 q4 = ((const float4*)(q + (size_t)bh * D_DIM))[lane];
        __syncthreads();

        const float scale = 0.08838834764831845f;  // 1/sqrt(128)

        float  m    = -1e30f;
        float  ssum = 0.0f;
        float4 acc  = make_float4(0.f, 0.f, 0.f, 0.f);

        // Warp w owns groups g = w, w+NWARPS, ...
        const int total_groups = (cnt + GSIZE - 1) >> 2;
        const int n_w = (total_groups > wid)
                      ? (total_groups - wid + NWARPS - 1) / NWARPS : 0;

        const unsigned ring_base = smem_u32(&s_ring[wid][0][0][0][0]) + lane * 16u;

        auto issue_group = [&](int t) {
            const int  l0   = (wid + t * NWARPS) * GSIZE;
            const unsigned slot = ring_base + (unsigned)(t & 1) * (2u * GSIZE * D_DIM * 4u);
            #pragma unroll
            for (int u = 0; u < GSIZE; u++) {
                const int  l     = l0 + u;
                const bool valid = (l < cnt);
                const int  i     = valid ? s_ind[l] : 0;
                const unsigned page = (unsigned)s_pages[i >> 4];
                const float* src = kv + ((page << 15)
                                       + ((unsigned)kvh << 11)
                                       + ((unsigned)(i & 15) << 7)
                                       + ((unsigned)lane << 2));
                const unsigned dk = slot + (unsigned)u * (D_DIM * 4u);
                const unsigned dv = dk + (unsigned)(GSIZE * D_DIM * 4u);
                if (valid) {
                    CP16(dk, src);
                    CP16(dv, src + KV_STRIDE);
                } else {
                    CP16_ZERO(dk, src);
                    CP16_ZERO(dv, src);
                }
            }
            CP_COMMIT();
        };

        if (n_w > 0) {
            issue_group(0);
            issue_group(1);

            for (int t = 0; t < n_w; t++) {
                CP_WAIT1();          // oldest group (t) complete
                __syncwarp();

                const int  l0   = (wid + t * NWARPS) * GSIZE;
                const int  slot = t & 1;

                float4 kk[GSIZE];
                #pragma unroll
                for (int u = 0; u < GSIZE; u++)
                    kk[u] = *(const float4*)&s_ring[wid][slot][0][u][lane * 4];

                float sc[GSIZE];
                #pragma unroll
                for (int u = 0; u < GSIZE; u++) {
                    float d = kk[u].x * q4.x + kk[u].y * q4.y
                            + kk[u].z * q4.z + kk[u].w * q4.w;
                    #pragma unroll
                    for (int o = 16; o > 0; o >>= 1)
                        d += __shfl_xor_sync(0xffffffffu, d, o);
                    sc[u] = (l0 + u < cnt) ? d * scale : -1e30f;
                }

                float4 vv[GSIZE];
                #pragma unroll
                for (int u = 0; u < GSIZE; u++)
                    vv[u] = *(const float4*)&s_ring[wid][slot][1][u][lane * 4];

                __syncwarp();        // all lanes done reading this stage
                issue_group(t + 2);  // refill stage

                float mnew = m;
                #pragma unroll
                for (int u = 0; u < GSIZE; u++) mnew = fmaxf(mnew, sc[u]);

                const float alpha = __expf(m - mnew);
                float p[GSIZE];
                float psum = 0.0f;
                #pragma unroll
                for (int u = 0; u < GSIZE; u++) {
                    p[u] = __expf(sc[u] - mnew);
                    psum += p[u];
                }

                acc.x *= alpha; acc.y *= alpha; acc.z *= alpha; acc.w *= alpha;
                #pragma unroll
                for (int u = 0; u < GSIZE; u++) {
                    acc.x += p[u] * vv[u].x;
                    acc.y += p[u] * vv[u].y;
                    acc.z += p[u] * vv[u].z;
                    acc.w += p[u] * vv[u].w;
                }
                ssum = ssum * alpha + psum;
                m    = mnew;
            }
        }
        CP_WAITALL();   // drain dummy in-flight groups before smem reuse/exit

        // Publish per-warp partials to smem
        s_acc[wid][lane * 4 + 0] = acc.x;
        s_acc[wid][lane * 4 + 1] = acc.y;
        s_acc[wid][lane * 4 + 2] = acc.z;
        s_acc[wid][lane * 4 + 3] = acc.w;
        if (lane == 0) { s_m[wid] = m; s_s[wid] = ssum; }
        __syncthreads();

        // Cross-warp merge -> global split-K partial (128 threads, one per d)
        {
            float M = -1e30f;
            #pragma unroll
            for (int w = 0; w < NWARPS; w++) M = fmaxf(M, s_m[w]);
            float denom = 0.f, num = 0.f;
            #pragma unroll
            for (int w = 0; w < NWARPS; w++) {
                const float c = __expf(s_m[w] - M);
                denom += c * s_s[w];
                num   += c * s_acc[w][tid];
            }
            g_acc[(size_t)blk * D_DIM + tid] = num;
            if (tid == 0) { g_m[blk] = M; g_s[blk] = denom; }
        }
    } else {
        // Empty tile: publish -inf max so merge weight underflows to exactly 0.
        // (stale g_s/g_acc are multiplied by exp(-1e30 - M) == 0 -> deterministic)
        if (tid == 0) g_m[blk] = -1e30f;
    }

    // Arrival protocol: last block of this bh does the final merge
    __syncthreads();
    if (tid == 0) {
        __threadfence();
        const unsigned old = atomicAdd(&g_cnt[bh], 1u);
        s_is_last = (old == SPLIT_MAX - 1);
        if (s_is_last) g_cnt[bh] = 0;   // reset for next graph replay
    }
    __syncthreads();

    if (s_is_last) {
        __threadfence();   // acquire: make other blocks' fenced writes visible
        const int base = bh * SPLIT_MAX;
        float M = -1e30f;
        #pragma unroll
        for (int s = 0; s < SPLIT_MAX; s++) M = fmaxf(M, g_m[base + s]);
        float denom = 0.f, num = 0.f;
        #pragma unroll
        for (int s = 0; s < SPLIT_MAX; s++) {
            const float c = __expf(g_m[base + s] - M);
            denom += c * g_s[base + s];
            num   += c * g_acc[(size_t)(base + s) * D_DIM + tid];
        }
        out[(size_t)bh * D_DIM + tid] = num / denom;
    }
}

extern "C" void kernel_launch(void* const* d_in, const int* in_sizes, int n_in,
                              void* d_out, int out_size) {
    const float* q            = (const float*)d_in[0];
    const float* kv           = (const float*)d_in[1];
    const int*   indptr       = (const int*)d_in[2];
    const int*   page_indices = (const int*)d_in[3];
    const int*   sparse_ind   = (const int*)d_in[4];
    const int*   sparse_nnz   = (const int*)d_in[5];
    float*       out          = (float*)d_out;

    sparse_attn_kernel<<<B_DIM * H_DIM * SPLIT_MAX, NTHREADS>>>(
        q, kv, indptr, page_indices, sparse_ind, sparse_nnz, out);
}